// round 16
// baseline (speedup 1.0000x reference)
#include <cuda_runtime.h>
#include <cuda_fp16.h>
#include <math.h>
#include <stdint.h>

#define DIM   1024
#define HMID  512
#define HLOW  256
#define MAXM  32768
#define NSTG  3

// ---------------- scratch (static device arrays; no allocations) ----------------
__device__ __half g_bufA[(size_t)MAXM * DIM];   // h0 (LN out, half), later h2
__device__ __half g_bufB[(size_t)MAXM * HMID];  // h1, later h3
__device__ __half g_w1[DIM * HMID];             // W1^T [HMID, DIM]  half
__device__ __half g_w2[HMID * HMID];            // W2^T [HMID, HMID]
__device__ __half g_w3[HMID * HLOW];            // W3^T [HLOW, HMID]
__device__ __half g_w4[HLOW * DIM];             // W4^T [DIM,  HLOW]

// ---------------- helpers ----------------
__device__ __forceinline__ float gelu_exact(float x) {
    return 0.5f * x * (1.0f + erff(x * 0.70710678118654752440f));
}
__device__ __forceinline__ void cp_async16_s(uint32_t saddr, const void* g) {
    asm volatile("cp.async.cg.shared.global [%0], [%1], 16;\n" :: "r"(saddr), "l"(g));
}
__device__ __forceinline__ uint32_t smem_u32(const void* p) {
    uint32_t a;
    asm("{ .reg .u64 t; cvta.to.shared.u64 t, %1; cvt.u32.u64 %0, t; }" : "=r"(a) : "l"(p));
    return a;
}
__device__ __forceinline__ void ldsm_x4(unsigned* r, uint32_t addr) {
    asm volatile("ldmatrix.sync.aligned.m8n8.x4.shared.b16 {%0,%1,%2,%3}, [%4];"
                 : "=r"(r[0]), "=r"(r[1]), "=r"(r[2]), "=r"(r[3]) : "r"(addr));
}

// ---------------- fused LN + weight transpose prep -----------------------------
// Blocks [0, M/8): LayerNorm, one warp per row. Blocks [M/8, M/8+1152): transpose.
__global__ void ln_prep(const float* __restrict__ x, const float* __restrict__ gamma,
                        const float* __restrict__ beta, __half* __restrict__ out, int M,
                        const float* __restrict__ W1, const float* __restrict__ W2,
                        const float* __restrict__ W3, const float* __restrict__ W4,
                        __half* __restrict__ w1, __half* __restrict__ w2,
                        __half* __restrict__ w3, __half* __restrict__ w4) {
    __shared__ float tile[32][33];
    const int lnBlocks = M / 8;
    if ((int)blockIdx.x >= lnBlocks) {
        // ---- weight transpose: W[K,N] -> Wt[N,K] half ----
        int b = blockIdx.x - lnBlocks;
        const float* W; __half* Wt; int K, N, id;
        if (b < 512)      { W = W1; Wt = w1; K = DIM;  N = HMID; id = b; }
        else if (b < 768) { W = W2; Wt = w2; K = HMID; N = HMID; id = b - 512; }
        else if (b < 896) { W = W3; Wt = w3; K = HMID; N = HLOW; id = b - 768; }
        else              { W = W4; Wt = w4; K = HLOW; N = DIM;  id = b - 896; }
        const int nTiles = N / 32;
        const int n0 = (id % nTiles) * 32;
        const int k0 = (id / nTiles) * 32;
        const int tx = threadIdx.x & 31, ty = threadIdx.x >> 5;   // 32 x 8
#pragma unroll
        for (int i = ty; i < 32; i += 8)
            tile[i][tx] = W[(size_t)(k0 + i) * N + n0 + tx];
        __syncthreads();
#pragma unroll
        for (int i = ty; i < 32; i += 8)
            Wt[(size_t)(n0 + i) * K + k0 + tx] = __float2half_rn(tile[tx][i]);
        return;
    }

    // ---- LayerNorm ----
    int warp = (int)((blockIdx.x * blockDim.x + threadIdx.x) >> 5);
    int lane = threadIdx.x & 31;

    const float4* xr = reinterpret_cast<const float4*>(x) + (size_t)warp * (DIM / 4);
    float4 v[8];
    float s = 0.f, ss = 0.f;
#pragma unroll
    for (int i = 0; i < 8; i++) {
        float4 t = xr[i * 32 + lane];
        v[i] = t;
        s  += t.x + t.y + t.z + t.w;
        ss += t.x * t.x + t.y * t.y + t.z * t.z + t.w * t.w;
    }
#pragma unroll
    for (int o = 16; o > 0; o >>= 1) {
        s  += __shfl_xor_sync(0xffffffffu, s,  o);
        ss += __shfl_xor_sync(0xffffffffu, ss, o);
    }
    float mu  = s * (1.0f / DIM);
    float var = ss * (1.0f / DIM) - mu * mu;
    float rs  = rsqrtf(var + 1e-5f);

    uint2* o8 = reinterpret_cast<uint2*>(out + (size_t)warp * DIM);
    const float4* g4 = reinterpret_cast<const float4*>(gamma);
    const float4* b4 = reinterpret_cast<const float4*>(beta);
#pragma unroll
    for (int i = 0; i < 8; i++) {
        float4 gv = g4[i * 32 + lane];
        float4 bv = b4[i * 32 + lane];
        float4 t = v[i];
        __half2 h0 = __floats2half2_rn((t.x - mu) * rs * gv.x + bv.x,
                                       (t.y - mu) * rs * gv.y + bv.y);
        __half2 h1 = __floats2half2_rn((t.z - mu) * rs * gv.z + bv.z,
                                       (t.w - mu) * rs * gv.w + bv.w);
        uint2 pk;
        pk.x = *reinterpret_cast<uint32_t*>(&h0);
        pk.y = *reinterpret_cast<uint32_t*>(&h1);
        o8[i * 32 + lane] = pk;
    }
}

// ---------------- fp16 GEMM: C = act(A[M,K](half) @ Bt[N,K](half)^T + bias) -----
// CTA tile 128x128, BK=64 halves (128B k-slab), 8 warps 2(M)x4(N), warp 64x32,
// m16n8k16.  smem rows padded to 72 halves (144B): conflict-free ldmatrix,
// minimal-phase cp.async.  3 stages x 36KB = 108KB dynamic smem, 2 CTAs/SM.
// ACT=1: GELU -> half C.  ACT=2: +bias +residual (L2-prefetched, .cs) -> fp32 C.
template<int ACT>
__global__ __launch_bounds__(256, 2)
void gemm_f16(const __half* __restrict__ A, const __half* __restrict__ Bt,
              const float* __restrict__ bias, const float* __restrict__ R,
              void* __restrict__ Cout, int K, int N) {
    extern __shared__ __align__(16) char sh[];
    const uint32_t sbase = smem_u32(sh);
    const uint32_t SBOFF = 128u * 144u;          // 18432: B offset within a stage
    const uint32_t STG   = 2u * 128u * 144u;     // 36864 per stage

    const int t    = threadIdx.x;
    const int lane = t & 31;
    const int warp = t >> 5;
    const int wm   = warp & 1;        // 0..1 -> M (64 rows each)
    const int wn   = warp >> 1;       // 0..3 -> N (32 cols each)
    const int g    = lane >> 2;       // 0..7
    const int t4   = lane & 3;        // 0..3
    const int bm   = blockIdx.y * 128;
    const int bn   = blockIdx.x * 128;
    const int KT   = K >> 6;          // K tiles of 64 halves

    // warm L2 with this CTA's residual region (read exactly once, in epilogue)
    if (ACT == 2) {
#pragma unroll
        for (int i = 0; i < 2; i++) {
            int line = t * 2 + i;                 // 0..511 = 128 rows x 4 x 128B
            const float* p = R + (size_t)(bm + (line >> 2)) * N + bn + (line & 3) * 32;
            asm volatile("prefetch.global.L2 [%0];" :: "l"(p));
        }
    }

    // per-lane ldmatrix base offsets (bytes, within a stage)
    const uint32_t aoff = (uint32_t)(wm * 64 + (lane & 15)) * 144u + (uint32_t)(lane >> 4) * 16u;
    const uint32_t boff = SBOFF + (uint32_t)(wn * 32 + ((lane >> 4) << 3) + (lane & 7)) * 144u
                        + (uint32_t)((lane >> 3) & 1) * 16u;

    // cp.async addressing: 8 chunks of 16B per 128B row; 1024 chunks per operand
    const int ldrow = t >> 3;         // 0..31
    const int ldch  = t & 7;          // 0..7

    auto load_tile = [&](int slot, int kt) {
        const uint32_t ab = sbase + slot * STG;
#pragma unroll
        for (int i = 0; i < 4; i++) {
            int row = ldrow + i * 32;
            cp_async16_s(ab + (uint32_t)row * 144u + (uint32_t)ldch * 16u,
                         A + (size_t)(bm + row) * K + kt * 64 + ldch * 8);
        }
#pragma unroll
        for (int i = 0; i < 4; i++) {
            int row = ldrow + i * 32;
            cp_async16_s(ab + SBOFF + (uint32_t)row * 144u + (uint32_t)ldch * 16u,
                         Bt + (size_t)(bn + row) * K + kt * 64 + ldch * 8);
        }
    };

    float acc[4][4][4];
#pragma unroll
    for (int mi = 0; mi < 4; mi++)
#pragma unroll
        for (int ni = 0; ni < 4; ni++)
#pragma unroll
            for (int r = 0; r < 4; r++) acc[mi][ni][r] = 0.f;

    auto mma_tile = [&](int slot) {
        const uint32_t stg = sbase + slot * STG;
#pragma unroll
        for (int kk = 0; kk < 4; kk++) {          // four k16 steps per 64-K slab
            unsigned af[4][4];
#pragma unroll
            for (int mi = 0; mi < 4; mi++)
                ldsm_x4(af[mi], stg + aoff + (uint32_t)mi * 2304u + (uint32_t)kk * 32u);
            unsigned bf[2][4];
#pragma unroll
            for (int nj = 0; nj < 2; nj++)
                ldsm_x4(bf[nj], stg + boff + (uint32_t)nj * 2304u + (uint32_t)kk * 32u);
#pragma unroll
            for (int mi = 0; mi < 4; mi++)
#pragma unroll
                for (int ni = 0; ni < 4; ni++) {
                    const unsigned b0 = bf[ni >> 1][(ni & 1) * 2 + 0];
                    const unsigned b1 = bf[ni >> 1][(ni & 1) * 2 + 1];
                    asm volatile(
                        "mma.sync.aligned.m16n8k16.row.col.f32.f16.f16.f32 "
                        "{%0,%1,%2,%3}, {%4,%5,%6,%7}, {%8,%9}, {%0,%1,%2,%3};\n"
                        : "+f"(acc[mi][ni][0]), "+f"(acc[mi][ni][1]),
                          "+f"(acc[mi][ni][2]), "+f"(acc[mi][ni][3])
                        : "r"(af[mi][0]), "r"(af[mi][1]), "r"(af[mi][2]), "r"(af[mi][3]),
                          "r"(b0), "r"(b1));
                }
        }
    };

    load_tile(0, 0);
    asm volatile("cp.async.commit_group;\n");
    load_tile(1, 1);
    asm volatile("cp.async.commit_group;\n");

    for (int kt = 0; kt < KT; kt++) {
        asm volatile("cp.async.wait_group 1;\n");
        __syncthreads();

        const int cur = kt % NSTG;
        const int nxt = kt + NSTG - 1;
        if (nxt < KT) load_tile((cur + NSTG - 1) % NSTG, nxt);
        asm volatile("cp.async.commit_group;\n");   // always commit: keep count exact

        mma_tile(cur);
    }

    // Epilogue: c0,c1 -> row g cols 2t4,2t4+1 ; c2,c3 -> row g+8.
    const int rb = bm + wm * 64;
    const int cb = bn + wn * 32;
#pragma unroll
    for (int ni = 0; ni < 4; ni++) {
        const int c0 = cb + ni * 8 + t4 * 2;
        const float bz0 = bias[c0], bz1 = bias[c0 + 1];
#pragma unroll
        for (int mi = 0; mi < 4; mi++) {
#pragma unroll
            for (int h = 0; h < 2; h++) {
                const int r = rb + mi * 16 + g + h * 8;
                float v0 = acc[mi][ni][h * 2 + 0] + bz0;
                float v1 = acc[mi][ni][h * 2 + 1] + bz1;
                if (ACT == 1) {
                    __half2 hv = __floats2half2_rn(gelu_exact(v0), gelu_exact(v1));
                    *reinterpret_cast<__half2*>(
                        reinterpret_cast<__half*>(Cout) + (size_t)r * N + c0) = hv;
                } else {
                    const size_t off = (size_t)r * N + c0;
                    float r0, r1;
                    asm("ld.global.cs.v2.f32 {%0,%1}, [%2];"
                        : "=f"(r0), "=f"(r1) : "l"(R + off));
                    v0 += r0;
                    v1 += r1;
                    asm volatile("st.global.cs.v2.f32 [%0], {%1,%2};"
                                 :: "l"(reinterpret_cast<float*>(Cout) + off),
                                    "f"(v0), "f"(v1));
                }
            }
        }
    }
}

// ---------------- launch ----------------
extern "C" void kernel_launch(void* const* d_in, const int* in_sizes, int n_in,
                              void* d_out, int out_size) {
    const float* x     = (const float*)d_in[0];
    const float* gamma = (const float*)d_in[1];
    const float* beta  = (const float*)d_in[2];
    const float* W1    = (const float*)d_in[3];
    const float* b1    = (const float*)d_in[4];
    const float* W2    = (const float*)d_in[5];
    const float* b2    = (const float*)d_in[6];
    const float* W3    = (const float*)d_in[7];
    const float* b3    = (const float*)d_in[8];
    const float* W4    = (const float*)d_in[9];
    const float* b4    = (const float*)d_in[10];
    float* out = (float*)d_out;

    const int M = in_sizes[0] / DIM;   // 32768

    __half *bufA, *bufB, *w1, *w2, *w3, *w4;
    cudaGetSymbolAddress((void**)&bufA, g_bufA);
    cudaGetSymbolAddress((void**)&bufB, g_bufB);
    cudaGetSymbolAddress((void**)&w1, g_w1);
    cudaGetSymbolAddress((void**)&w2, g_w2);
    cudaGetSymbolAddress((void**)&w3, g_w3);
    cudaGetSymbolAddress((void**)&w4, g_w4);

    const int smem_bytes = NSTG * 2 * 128 * 144;   // 110592
    cudaFuncSetAttribute(gemm_f16<1>, cudaFuncAttributeMaxDynamicSharedMemorySize, smem_bytes);
    cudaFuncSetAttribute(gemm_f16<2>, cudaFuncAttributeMaxDynamicSharedMemorySize, smem_bytes);

    ln_prep<<<M / 8 + 1152, 256>>>(x, gamma, beta, bufA, M,
                                   W1, W2, W3, W4, w1, w2, w3, w4);

    gemm_f16<1><<<dim3(HMID / 128, M / 128), 256, smem_bytes>>>(bufA, w1, b1, nullptr, bufB, DIM,  HMID); // h1
    gemm_f16<1><<<dim3(HMID / 128, M / 128), 256, smem_bytes>>>(bufB, w2, b2, nullptr, bufA, HMID, HMID); // h2
    gemm_f16<1><<<dim3(HLOW / 128, M / 128), 256, smem_bytes>>>(bufA, w3, b3, nullptr, bufB, HMID, HLOW); // h3
    gemm_f16<2><<<dim3(DIM  / 128, M / 128), 256, smem_bytes>>>(bufB, w4, b4, x,       out,  HLOW, DIM);  // out
}

// round 17
// speedup vs baseline: 1.2152x; 1.2152x over previous
#include <cuda_runtime.h>
#include <cuda_fp16.h>
#include <math.h>
#include <stdint.h>

#define DIM   1024
#define HMID  512
#define HLOW  256
#define MAXM  32768

// ---------------- scratch (static device arrays; no allocations) ----------------
__device__ __half g_bufA[(size_t)MAXM * DIM];   // h0 (LN out, half), later h2
__device__ __half g_bufB[(size_t)MAXM * HMID];  // h1, later h3
__device__ __half g_w1[DIM * HMID];             // W1^T [HMID, DIM]  half
__device__ __half g_w2[HMID * HMID];            // W2^T [HMID, HMID]
__device__ __half g_w3[HMID * HLOW];            // W3^T [HLOW, HMID]
__device__ __half g_w4[HLOW * DIM];             // W4^T [DIM,  HLOW]

// ---------------- helpers ----------------
__device__ __forceinline__ float gelu_exact(float x) {
    return 0.5f * x * (1.0f + erff(x * 0.70710678118654752440f));
}
__device__ __forceinline__ void cp_async16_s(uint32_t saddr, const void* g) {
    asm volatile("cp.async.cg.shared.global [%0], [%1], 16;\n" :: "r"(saddr), "l"(g));
}
__device__ __forceinline__ uint32_t smem_u32(const void* p) {
    uint32_t a;
    asm("{ .reg .u64 t; cvta.to.shared.u64 t, %1; cvt.u32.u64 %0, t; }" : "=r"(a) : "l"(p));
    return a;
}
__device__ __forceinline__ void ldsm_x4(unsigned* r, uint32_t addr) {
    asm volatile("ldmatrix.sync.aligned.m8n8.x4.shared.b16 {%0,%1,%2,%3}, [%4];"
                 : "=r"(r[0]), "=r"(r[1]), "=r"(r[2]), "=r"(r[3]) : "r"(addr));
}

// ---------------- prep: transpose all 4 weights to [N,K] half, one kernel -------
__global__ void prep_all(const float* __restrict__ W1, const float* __restrict__ W2,
                         const float* __restrict__ W3, const float* __restrict__ W4,
                         __half* __restrict__ w1, __half* __restrict__ w2,
                         __half* __restrict__ w3, __half* __restrict__ w4) {
    __shared__ float tile[32][33];
    int b = blockIdx.x;
    const float* W; __half* Wt; int K, N, id;
    if (b < 512)            { W = W1; Wt = w1; K = DIM;  N = HMID; id = b; }
    else if (b < 768)       { W = W2; Wt = w2; K = HMID; N = HMID; id = b - 512; }
    else if (b < 896)       { W = W3; Wt = w3; K = HMID; N = HLOW; id = b - 768; }
    else                    { W = W4; Wt = w4; K = HLOW; N = DIM;  id = b - 896; }
    const int nTiles = N / 32;
    const int n0 = (id % nTiles) * 32;
    const int k0 = (id / nTiles) * 32;
    const int tx = threadIdx.x, ty = threadIdx.y;   // 32 x 8
#pragma unroll
    for (int i = ty; i < 32; i += 8)
        tile[i][tx] = W[(size_t)(k0 + i) * N + n0 + tx];
    __syncthreads();
#pragma unroll
    for (int i = ty; i < 32; i += 8)
        Wt[(size_t)(n0 + i) * K + k0 + tx] = __float2half_rn(tile[tx][i]);
}

// ---------------- LayerNorm: one warp per row of 1024, half output -------------
__global__ void ln_kernel(const float* __restrict__ x, const float* __restrict__ gamma,
                          const float* __restrict__ beta, __half* __restrict__ out, int M) {
    int warp = (int)((blockIdx.x * blockDim.x + threadIdx.x) >> 5);
    int lane = threadIdx.x & 31;
    if (warp >= M) return;

    const float4* xr = reinterpret_cast<const float4*>(x) + (size_t)warp * (DIM / 4);
    float4 v[8];
    float s = 0.f, ss = 0.f;
#pragma unroll
    for (int i = 0; i < 8; i++) {
        float4 t = xr[i * 32 + lane];
        v[i] = t;
        s  += t.x + t.y + t.z + t.w;
        ss += t.x * t.x + t.y * t.y + t.z * t.z + t.w * t.w;
    }
#pragma unroll
    for (int o = 16; o > 0; o >>= 1) {
        s  += __shfl_xor_sync(0xffffffffu, s,  o);
        ss += __shfl_xor_sync(0xffffffffu, ss, o);
    }
    float mu  = s * (1.0f / DIM);
    float var = ss * (1.0f / DIM) - mu * mu;
    float rs  = rsqrtf(var + 1e-5f);

    uint2* o8 = reinterpret_cast<uint2*>(out + (size_t)warp * DIM);
    const float4* g4 = reinterpret_cast<const float4*>(gamma);
    const float4* b4 = reinterpret_cast<const float4*>(beta);
#pragma unroll
    for (int i = 0; i < 8; i++) {
        float4 gv = g4[i * 32 + lane];
        float4 bv = b4[i * 32 + lane];
        float4 t = v[i];
        __half2 h0 = __floats2half2_rn((t.x - mu) * rs * gv.x + bv.x,
                                       (t.y - mu) * rs * gv.y + bv.y);
        __half2 h1 = __floats2half2_rn((t.z - mu) * rs * gv.z + bv.z,
                                       (t.w - mu) * rs * gv.w + bv.w);
        uint2 pk;
        pk.x = *reinterpret_cast<uint32_t*>(&h0);
        pk.y = *reinterpret_cast<uint32_t*>(&h1);
        o8[i * 32 + lane] = pk;
    }
}

// ---------------- fp16 GEMM: C = act(A[M,K](half) @ Bt[N,K](half)^T + bias) -----
// CTA tile 128x128, 8 warps 2(M)x4(N), warp tile 64x32, m16n8k16.
// Templated k-slab BK (halves) and stage count NST:
//   BK=64: rows padded to 144B (R15-proven conflict-free layout), NST=3.
//   BK=32: rows padded to  80B (R12-proven conflict-free layout), NST=4
//          (prologue NST-1 tiles -> 2-tile load lookahead at each wait).
// ACT=1: GELU -> half C.  ACT=2: +bias +residual -> fp32 C.
template<int ACT, int BK, int NST>
__global__ __launch_bounds__(256, 2)
void gemm_f16(const __half* __restrict__ A, const __half* __restrict__ Bt,
              const float* __restrict__ bias, const float* __restrict__ R,
              void* __restrict__ Cout, int K, int N) {
    constexpr int ROWB = 2 * BK + 16;            // bytes per padded smem row
    constexpr int CH   = BK / 8;                 // 16B chunks per row
    constexpr int RPP  = 256 / CH;               // rows covered per pass
    constexpr int LIT  = 128 / RPP;              // loader iterations per operand
    constexpr int KKS  = BK / 16;                // k16 steps per slab
    const uint32_t SBOFF = 128u * ROWB;
    const uint32_t STG   = 2u * 128u * ROWB;

    extern __shared__ __align__(16) char sh[];
    const uint32_t sbase = smem_u32(sh);

    const int t    = threadIdx.x;
    const int lane = t & 31;
    const int warp = t >> 5;
    const int wm   = warp & 1;        // 0..1 -> M (64 rows each)
    const int wn   = warp >> 1;       // 0..3 -> N (32 cols each)
    const int g    = lane >> 2;       // 0..7
    const int t4   = lane & 3;        // 0..3
    const int bm   = blockIdx.y * 128;
    const int bn   = blockIdx.x * 128;
    const int KT   = K / BK;

    // per-lane ldmatrix base offsets (bytes, within a stage)
    const uint32_t aoff = (uint32_t)(wm * 64 + (lane & 15)) * ROWB + (uint32_t)(lane >> 4) * 16u;
    const uint32_t boff = SBOFF + (uint32_t)(wn * 32 + ((lane >> 4) << 3) + (lane & 7)) * ROWB
                        + (uint32_t)((lane >> 3) & 1) * 16u;

    const int ldrow = t / CH;
    const int ldch  = t % CH;

    auto load_tile = [&](int slot, int kt) {
        const uint32_t ab = sbase + slot * STG;
#pragma unroll
        for (int i = 0; i < LIT; i++) {
            int row = ldrow + i * RPP;
            cp_async16_s(ab + (uint32_t)row * ROWB + (uint32_t)ldch * 16u,
                         A + (size_t)(bm + row) * K + kt * BK + ldch * 8);
        }
#pragma unroll
        for (int i = 0; i < LIT; i++) {
            int row = ldrow + i * RPP;
            cp_async16_s(ab + SBOFF + (uint32_t)row * ROWB + (uint32_t)ldch * 16u,
                         Bt + (size_t)(bn + row) * K + kt * BK + ldch * 8);
        }
    };

    float acc[4][4][4];
#pragma unroll
    for (int mi = 0; mi < 4; mi++)
#pragma unroll
        for (int ni = 0; ni < 4; ni++)
#pragma unroll
            for (int r = 0; r < 4; r++) acc[mi][ni][r] = 0.f;

    auto mma_tile = [&](int slot) {
        const uint32_t stg = sbase + slot * STG;
#pragma unroll
        for (int kk = 0; kk < KKS; kk++) {
            unsigned af[4][4];
#pragma unroll
            for (int mi = 0; mi < 4; mi++)
                ldsm_x4(af[mi], stg + aoff + (uint32_t)(mi * 16 * ROWB) + (uint32_t)kk * 32u);
            unsigned bf[2][4];
#pragma unroll
            for (int nj = 0; nj < 2; nj++)
                ldsm_x4(bf[nj], stg + boff + (uint32_t)(nj * 16 * ROWB) + (uint32_t)kk * 32u);
#pragma unroll
            for (int mi = 0; mi < 4; mi++)
#pragma unroll
                for (int ni = 0; ni < 4; ni++) {
                    const unsigned b0 = bf[ni >> 1][(ni & 1) * 2 + 0];
                    const unsigned b1 = bf[ni >> 1][(ni & 1) * 2 + 1];
                    asm volatile(
                        "mma.sync.aligned.m16n8k16.row.col.f32.f16.f16.f32 "
                        "{%0,%1,%2,%3}, {%4,%5,%6,%7}, {%8,%9}, {%0,%1,%2,%3};\n"
                        : "+f"(acc[mi][ni][0]), "+f"(acc[mi][ni][1]),
                          "+f"(acc[mi][ni][2]), "+f"(acc[mi][ni][3])
                        : "r"(af[mi][0]), "r"(af[mi][1]), "r"(af[mi][2]), "r"(af[mi][3]),
                          "r"(b0), "r"(b1));
                }
        }
    };

    // prologue: NST-1 tiles in flight
#pragma unroll
    for (int s = 0; s < NST - 1; s++) {
        load_tile(s, s);
        asm volatile("cp.async.commit_group;\n");
    }

    // invariant: before iter kt, committed groups = (NST-1) + kt.
    // wait_group 1 -> tiles <= kt + NST - 3 retired (>= kt).  Prefetch tile
    // kt+NST-1 reuses the slot of tile kt-1, retired before this barrier.
    for (int kt = 0; kt < KT; kt++) {
        asm volatile("cp.async.wait_group 1;\n");
        __syncthreads();

        const int cur = kt % NST;
        const int nxt = kt + NST - 1;
        if (nxt < KT) load_tile(nxt % NST, nxt);
        asm volatile("cp.async.commit_group;\n");   // always commit: keep count exact

        mma_tile(cur);
    }

    // Epilogue: c0,c1 -> row g cols 2t4,2t4+1 ; c2,c3 -> row g+8.
    const int rb = bm + wm * 64;
    const int cb = bn + wn * 32;
#pragma unroll
    for (int ni = 0; ni < 4; ni++) {
        const int c0 = cb + ni * 8 + t4 * 2;
        const float bz0 = bias[c0], bz1 = bias[c0 + 1];
#pragma unroll
        for (int mi = 0; mi < 4; mi++) {
#pragma unroll
            for (int h = 0; h < 2; h++) {
                const int r = rb + mi * 16 + g + h * 8;
                float v0 = acc[mi][ni][h * 2 + 0] + bz0;
                float v1 = acc[mi][ni][h * 2 + 1] + bz1;
                if (ACT == 1) {
                    __half2 hv = __floats2half2_rn(gelu_exact(v0), gelu_exact(v1));
                    *reinterpret_cast<__half2*>(
                        reinterpret_cast<__half*>(Cout) + (size_t)r * N + c0) = hv;
                } else {
                    const size_t off = (size_t)r * N + c0;
                    v0 += R[off];
                    v1 += R[off + 1];
                    *reinterpret_cast<float2*>(
                        reinterpret_cast<float*>(Cout) + off) = make_float2(v0, v1);
                }
            }
        }
    }
}

// ---------------- launch ----------------
extern "C" void kernel_launch(void* const* d_in, const int* in_sizes, int n_in,
                              void* d_out, int out_size) {
    const float* x     = (const float*)d_in[0];
    const float* gamma = (const float*)d_in[1];
    const float* beta  = (const float*)d_in[2];
    const float* W1    = (const float*)d_in[3];
    const float* b1    = (const float*)d_in[4];
    const float* W2    = (const float*)d_in[5];
    const float* b2    = (const float*)d_in[6];
    const float* W3    = (const float*)d_in[7];
    const float* b3    = (const float*)d_in[8];
    const float* W4    = (const float*)d_in[9];
    const float* b4    = (const float*)d_in[10];
    float* out = (float*)d_out;

    const int M = in_sizes[0] / DIM;   // 32768

    __half *bufA, *bufB, *w1, *w2, *w3, *w4;
    cudaGetSymbolAddress((void**)&bufA, g_bufA);
    cudaGetSymbolAddress((void**)&bufB, g_bufB);
    cudaGetSymbolAddress((void**)&w1, g_w1);
    cudaGetSymbolAddress((void**)&w2, g_w2);
    cudaGetSymbolAddress((void**)&w3, g_w3);
    cudaGetSymbolAddress((void**)&w4, g_w4);

    const int smem64 = 3 * 2 * 128 * 144;   // 110592 (BK=64, NST=3)
    const int smem32 = 4 * 2 * 128 * 80;    //  81920 (BK=32, NST=4)
    cudaFuncSetAttribute((gemm_f16<1, 64, 3>), cudaFuncAttributeMaxDynamicSharedMemorySize, smem64);
    cudaFuncSetAttribute((gemm_f16<1, 32, 4>), cudaFuncAttributeMaxDynamicSharedMemorySize, smem32);
    cudaFuncSetAttribute((gemm_f16<2, 32, 4>), cudaFuncAttributeMaxDynamicSharedMemorySize, smem32);

    prep_all<<<1152, dim3(32, 8)>>>(W1, W2, W3, W4, w1, w2, w3, w4);
    ln_kernel<<<M / 8, 256>>>(x, gamma, beta, bufA, M);

    gemm_f16<1, 64, 3><<<dim3(HMID / 128, M / 128), 256, smem64>>>(bufA, w1, b1, nullptr, bufB, DIM,  HMID); // h1
    gemm_f16<1, 32, 4><<<dim3(HMID / 128, M / 128), 256, smem32>>>(bufB, w2, b2, nullptr, bufA, HMID, HMID); // h2
    gemm_f16<1, 32, 4><<<dim3(HLOW / 128, M / 128), 256, smem32>>>(bufA, w3, b3, nullptr, bufB, HMID, HLOW); // h3
    gemm_f16<2, 32, 4><<<dim3(DIM  / 128, M / 128), 256, smem32>>>(bufB, w4, b4, x,       out,  HLOW, DIM);  // out
}